// round 12
// baseline (speedup 1.0000x reference)
#include <cuda_runtime.h>
#include <cuda_fp16.h>
#include <cstdint>

// ============================================================================
// VCLinear: out[b,e] = sum_c basis_c(t_b) * (feats @ W_c)[b,e] + bias[e]
//
// Spline identity: per knot interval I, out[b] = sum_p t^p (feats @ P_p^I) + b.
// R12: chunk inner-loop restructure. Load ALL A fragments (both k16) up
// front, then powers p=0,1,2 each run 32 consecutive MMAs (2 k16 x 16),
// with ONE progressive ah*=t rescale between powers (2 serialization points
// per chunk vs 4). Same hmul count, 2x the independent MMAs covering each
// rescale chain. Target: tensor 69% -> ~80%.
// ============================================================================

#define M_TOTAL   32768
#define N_TOTAL   1024
#define LDX       1025
#define PAD_M     33280
#define MAX_TILES 260

#define M_TILE    128
#define N_TILE    128
#define THREADS   256
#define D_CHUNKS  32                 // 1024 / 32
#define K_DC      32                 // K per d-chunk

// smem: A ring 3 x 8K | B ring 9 x 8K | perm | t
#define SM_B        24576
#define SM_PERM     98304
#define SM_T        98816
#define SMEM_TOTAL  99328

// -------- device scratch --------
__device__ __align__(16) __half g_A[(size_t)M_TOTAL * 1024];
__device__ __align__(16) __half g_P[(size_t)4 * 3072 * N_TOTAL];  // 25 MB
__device__ int   g_perm[PAD_M];
__device__ float g_tp[PAD_M];
__device__ int   g_tile_int[MAX_TILES];

// -------- helpers --------
__device__ __forceinline__ uint32_t smem_u32(const void* p) {
    uint32_t a;
    asm("{ .reg .u64 t; cvta.to.shared.u64 t, %1; cvt.u32.u64 %0, t; }"
        : "=r"(a) : "l"(p));
    return a;
}

// A tile 128 rows x 32 halfs (64B/row) packed as 64 double-rows of 128B.
// chunk = (m&1)*4 + k/8; chunk ^= (m>>1)&7 -> ldmatrix phases conflict-free.
__device__ __forceinline__ uint32_t swzA32(int m, int k) {
    const uint32_t chunk = (uint32_t)(((m & 1) << 2) | ((k >> 3) & 3));
    const uint32_t dr = (uint32_t)(m >> 1);
    return dr * 128 + ((chunk ^ (dr & 7)) << 4) + (uint32_t)(k & 7) * 2;
}
// B tile 32 k-rows x 128 n (256B/row): chunk' = chunk ^ (k&7)  (proven).
__device__ __forceinline__ uint32_t swzB(int k, int n) {
    return (uint32_t)(k * 256 + ((((n >> 3) ^ (k & 7)) & 15) << 4) + (n & 7) * 2);
}

__device__ __forceinline__ void cp16(uint32_t dst, const void* src) {
    asm volatile("cp.async.cg.shared.global [%0], [%1], 16;"
                 :: "r"(dst), "l"(src) : "memory");
}

#define CP_COMMIT() asm volatile("cp.async.commit_group;" ::: "memory")
#define CP_WAIT(n)  asm volatile("cp.async.wait_group %0;" :: "n"(n) : "memory")

#define LDSM_X4(r0, r1, r2, r3, addr) \
    asm volatile("ldmatrix.sync.aligned.m8n8.x4.shared.b16 {%0,%1,%2,%3}, [%4];" \
                 : "=r"(r0), "=r"(r1), "=r"(r2), "=r"(r3) : "r"(addr))
#define LDSM_X4T(r0, r1, r2, r3, addr) \
    asm volatile("ldmatrix.sync.aligned.m8n8.x4.trans.shared.b16 {%0,%1,%2,%3}, [%4];" \
                 : "=r"(r0), "=r"(r1), "=r"(r2), "=r"(r3) : "r"(addr))

__device__ __forceinline__ void mma16816(float* c, const uint32_t* a, const uint32_t* b) {
    asm volatile(
        "mma.sync.aligned.m16n8k16.row.col.f32.f16.f16.f32 "
        "{%0,%1,%2,%3}, {%4,%5,%6,%7}, {%8,%9}, {%0,%1,%2,%3};"
        : "+f"(c[0]), "+f"(c[1]), "+f"(c[2]), "+f"(c[3])
        : "r"(a[0]), "r"(a[1]), "r"(a[2]), "r"(a[3]), "r"(b[0]), "r"(b[1]));
}

__device__ __forceinline__ uint32_t hmul2u(uint32_t a, uint32_t b) {
    __half2 r = __hmul2(*reinterpret_cast<__half2*>(&a),
                        *reinterpret_cast<__half2*>(&b));
    return *reinterpret_cast<uint32_t*>(&r);
}

// -------- pre-kernel: feats fp32 -> fp16 --------
__global__ void __launch_bounds__(256) split_a_kernel(const float* __restrict__ x) {
    size_t i = ((size_t)blockIdx.x * blockDim.x + threadIdx.x) * 4;
    if (i < (size_t)M_TOTAL * 1024) {
        const size_t m = i >> 10;
        const size_t d = i & 1023;
        const float* p = x + m * LDX + d;   // stride 1025: no LDG.128 allowed
        *reinterpret_cast<__half2*>(g_A + i)     = __floats2half2_rn(p[0], p[1]);
        *reinterpret_cast<__half2*>(g_A + i + 2) = __floats2half2_rn(p[2], p[3]);
    }
}

// -------- pre-kernel: build P (4 intervals x 3 powers) --------
__global__ void __launch_bounds__(256) build_p_kernel(const float* __restrict__ w) {
    const size_t idx = (size_t)blockIdx.x * 256 + threadIdx.x;  // d*1024+e
    if (idx >= (size_t)1 << 20) return;
    const float w0 = w[idx];
    const float w1 = w[(size_t)1 * 1048576 + idx];
    const float w2 = w[(size_t)2 * 1048576 + idx];
    const float w3 = w[(size_t)3 * 1048576 + idx];
    const float w4 = w[(size_t)4 * 1048576 + idx];
    const float w5 = w[(size_t)5 * 1048576 + idx];
    float p0 = w0, p1 = w1, p2 = w2;
    #pragma unroll
    for (int i = 0; i < 4; ++i) {
        const size_t base = (size_t)i * 3 * 1048576 + idx;
        g_P[base]               = __float2half_rn(p0);
        g_P[base + 1048576]     = __float2half_rn(p1);
        g_P[base + 2 * 1048576] = __float2half_rn(p2);
        if (i == 0) { p0 += 0.0625f * w3; p1 -= 0.5f * w3; p2 += w3; }
        if (i == 1) { p0 += 0.25f   * w4; p1 -= 1.0f * w4; p2 += w4; }
        if (i == 2) { p0 += 0.5625f * w5; p1 -= 1.5f * w5; p2 += w5; }
    }
}

// -------- bucket kernel (1 CTA, smem t-cache) --------
__global__ void __launch_bounds__(1024) bucket_kernel(const float* __restrict__ x) {
    extern __shared__ float t_cache[];
    __shared__ int s_cnt[4], s_cur[4];
    const int tid = threadIdx.x;
    if (tid < 4) s_cnt[tid] = 0;
    for (int i = tid; i < PAD_M; i += 1024) g_perm[i] = -1;
    for (int i = tid; i < MAX_TILES; i += 1024) g_tile_int[i] = -1;
    for (int i = tid; i < M_TOTAL; i += 1024)
        t_cache[i] = x[(size_t)i * LDX + 1024];
    __syncthreads();

    const int base = tid * 32;
    int c[4] = {0, 0, 0, 0};
    #pragma unroll 4
    for (int r = 0; r < 32; ++r) {
        const float t = t_cache[base + r];
        c[(t > 0.25f) + (t > 0.5f) + (t > 0.75f)]++;
    }
    #pragma unroll
    for (int i = 0; i < 4; ++i) atomicAdd(&s_cnt[i], c[i]);
    __syncthreads();

    if (tid == 0) {
        int s = 0;
        #pragma unroll
        for (int i = 0; i < 4; ++i) {
            const int nt = (s_cnt[i] + 127) >> 7;
            const int ts = s >> 7;
            for (int j = 0; j < nt; ++j) g_tile_int[ts + j] = i;
            s_cur[i] = s;
            s += nt * 128;
        }
    }
    __syncthreads();

    int my[4];
    #pragma unroll
    for (int i = 0; i < 4; ++i) my[i] = atomicAdd(&s_cur[i], c[i]);
    for (int r = 0; r < 32; ++r) {
        const float t = t_cache[base + r];
        const int iv = (t > 0.25f) + (t > 0.5f) + (t > 0.75f);
        const int pos = my[iv]++;
        g_perm[pos] = base + r;
        g_tp[pos] = t;
    }
}

// -------- per-d-chunk loader: A (8K) + 3 B tiles (24K) --------
__device__ __forceinline__ void load_chunk(uint32_t sb, int j,
                                           const int* __restrict__ perm_s,
                                           const __half* __restrict__ Pbase,
                                           int n0, int tid) {
    const int d0 = j * K_DC;
    const uint32_t aBase = sb + (uint32_t)(j % 3) * 8192;
    #pragma unroll
    for (int r = 0; r < 2; ++r) {
        const int task = tid + r * 256;
        const int m = task >> 2;
        const int kc = task & 3;
        const int rg = perm_s[m] < 0 ? 0 : perm_s[m];
        cp16(aBase + swzA32(m, kc * 8), g_A + (size_t)rg * 1024 + d0 + kc * 8);
    }
    #pragma unroll
    for (int p = 0; p < 3; ++p) {
        const uint32_t bBase = sb + SM_B + (uint32_t)((j % 3) * 3 + p) * 8192;
        const __half* src = Pbase + (size_t)(p * 1024 + d0) * N_TOTAL + n0;
        #pragma unroll
        for (int r = 0; r < 2; ++r) {
            const int task = tid + r * 256;
            const int k = task >> 4;
            const int c = task & 15;
            cp16(bBase + swzB(k, c * 8), src + (size_t)k * N_TOTAL + c * 8);
        }
    }
}

// -------- main GEMM kernel: 2 CTAs/SM --------
__global__ void __launch_bounds__(THREADS, 2)
vclinear_gemm(const float* __restrict__ bias,
              float* __restrict__ out) {
    const int mt = blockIdx.x >> 3;
    const int interval = g_tile_int[mt];
    if (interval < 0) return;
    const int n0 = (blockIdx.x & 7) * N_TILE;

    extern __shared__ char smem[];
    const uint32_t sb = smem_u32(smem);
    const int tid = threadIdx.x;
    const int wid = tid >> 5;
    const int lane = tid & 31;
    const int warp_m = wid & 1;
    const int warp_n = wid >> 1;

    int* perm_s = reinterpret_cast<int*>(smem + SM_PERM);
    float* t_s  = reinterpret_cast<float*>(smem + SM_T);
    if (tid < M_TILE) {
        perm_s[tid] = g_perm[mt * M_TILE + tid];
        t_s[tid]    = g_tp[mt * M_TILE + tid];
    }
    __syncthreads();

    const __half* Pbase = g_P + (size_t)interval * 3072 * N_TOTAL;

    load_chunk(sb, 0, perm_s, Pbase, n0, tid);
    CP_COMMIT();
    load_chunk(sb, 1, perm_s, Pbase, n0, tid);
    CP_COMMIT();

    float acc[4][4][4];
    #pragma unroll
    for (int a = 0; a < 4; ++a)
        #pragma unroll
        for (int b = 0; b < 4; ++b)
            #pragma unroll
            for (int i = 0; i < 4; ++i) acc[a][b][i] = 0.0f;

    const int a_row   = warp_m * 64 + (lane & 15);
    const int a_koct  = (lane >> 4) * 8;
    const int b_krow  = (lane & 7) + (lane & 8);
    const int b_nhalf = (lane >> 4) * 8;
    const int t_row   = warp_m * 64 + (lane >> 2);

    // t broadcast (half2) for fragment rows r (bT0) and r+8 (bT1)
    uint32_t bT0[4], bT1[4];
    #pragma unroll
    for (int m = 0; m < 4; ++m) {
        __half2 h0 = __float2half2_rn(t_s[t_row + m * 16]);
        __half2 h1 = __float2half2_rn(t_s[t_row + m * 16 + 8]);
        bT0[m] = *reinterpret_cast<uint32_t*>(&h0);
        bT1[m] = *reinterpret_cast<uint32_t*>(&h1);
    }

    for (int j = 0; j < D_CHUNKS; ++j) {
        CP_WAIT(1);
        __syncthreads();

        if (j + 2 < D_CHUNKS)
            load_chunk(sb, j + 2, perm_s, Pbase, n0, tid);
        CP_COMMIT();

        const uint32_t aBase  = sb + (uint32_t)(j % 3) * 8192;
        const uint32_t bBase0 = sb + SM_B + (uint32_t)((j % 3) * 3) * 8192;

        // load ALL A fragments for this chunk (both k16 steps): 8x LDSM_X4
        uint32_t ah[2][4][4];
        #pragma unroll
        for (int ks = 0; ks < 2; ++ks)
            #pragma unroll
            for (int m = 0; m < 4; ++m) {
                const uint32_t off = swzA32(a_row + m * 16, ks * 16 + a_koct);
                LDSM_X4(ah[ks][m][0], ah[ks][m][1],
                        ah[ks][m][2], ah[ks][m][3], aBase + off);
            }

        // powers p = 0,1,2: 32 consecutive MMAs each, 1 rescale between
        #pragma unroll
        for (int p = 0; p < 3; ++p) {
            const uint32_t bBase = bBase0 + (uint32_t)p * 8192;
            #pragma unroll
            for (int ks = 0; ks < 2; ++ks) {
                const int k0 = ks * 16;
                uint32_t bh[4][2];
                #pragma unroll
                for (int bt = 0; bt < 2; ++bt) {
                    const int n = warp_n * 32 + bt * 16 + b_nhalf;
                    const uint32_t off = swzB(k0 + b_krow, n);
                    LDSM_X4T(bh[2 * bt][0], bh[2 * bt][1],
                             bh[2 * bt + 1][0], bh[2 * bt + 1][1], bBase + off);
                }
                #pragma unroll
                for (int m = 0; m < 4; ++m)
                    #pragma unroll
                    for (int n = 0; n < 4; ++n)
                        mma16816(acc[m][n], ah[ks][m], bh[n]);
            }
            if (p < 2) {
                // progressive scale: ah *= t (p1 sees t, p2 sees t^2)
                #pragma unroll
                for (int ks = 0; ks < 2; ++ks)
                    #pragma unroll
                    for (int m = 0; m < 4; ++m) {
                        ah[ks][m][0] = hmul2u(ah[ks][m][0], bT0[m]);
                        ah[ks][m][1] = hmul2u(ah[ks][m][1], bT1[m]);
                        ah[ks][m][2] = hmul2u(ah[ks][m][2], bT0[m]);
                        ah[ks][m][3] = hmul2u(ah[ks][m][3], bT1[m]);
                    }
            }
        }
    }

    // epilogue: scatter rows via perm, add bias
    #pragma unroll
    for (int m = 0; m < 4; ++m) {
        #pragma unroll
        for (int half = 0; half < 2; ++half) {
            const int rl = warp_m * 64 + m * 16 + (lane >> 2) + half * 8;
            const int rg = perm_s[rl];
            if (rg < 0) continue;
            float* orow = out + (size_t)rg * N_TOTAL;
            #pragma unroll
            for (int n = 0; n < 4; ++n) {
                const int col = n0 + warp_n * 32 + n * 8 + (lane & 3) * 2;
                float2 v;
                v.x = acc[m][n][half * 2 + 0] + __ldg(bias + col);
                v.y = acc[m][n][half * 2 + 1] + __ldg(bias + col + 1);
                *reinterpret_cast<float2*>(orow + col) = v;
            }
        }
    }
}

// -------- launch --------
extern "C" void kernel_launch(void* const* d_in, const int* in_sizes, int n_in,
                              void* d_out, int out_size) {
    const float* x    = (const float*)d_in[0];   // (32768, 1025)
    const float* w    = (const float*)d_in[1];   // (6,1024,1024)
    const float* bias = (const float*)d_in[2];   // (1024,)
    float* out = (float*)d_out;                  // (32768, 1024)

    static bool attr_set = false;
    if (!attr_set) {
        cudaFuncSetAttribute(vclinear_gemm,
                             cudaFuncAttributeMaxDynamicSharedMemorySize, SMEM_TOTAL);
        cudaFuncSetAttribute(bucket_kernel,
                             cudaFuncAttributeMaxDynamicSharedMemorySize,
                             M_TOTAL * (int)sizeof(float));
        attr_set = true;
    }

    split_a_kernel<<<(M_TOTAL * 1024 / 4 + 255) / 256, 256>>>(x);
    bucket_kernel<<<1, 1024, M_TOTAL * sizeof(float)>>>(x);
    build_p_kernel<<<(1 << 20) / 256, 256>>>(w);

    vclinear_gemm<<<MAX_TILES * 8, THREADS, SMEM_TOTAL>>>(bias, out);
}

// round 13
// speedup vs baseline: 1.1666x; 1.1666x over previous
#include <cuda_runtime.h>
#include <cuda_fp16.h>
#include <cstdint>

// ============================================================================
// VCLinear: out[b,e] = sum_c basis_c(t_b) * (feats @ W_c)[b,e] + bias[e]
//
// Spline identity: per knot interval I, out[b] = sum_p t^p (feats @ P_p^I) + b.
// R13 (after R12 spill regression -> reverted to R11 loop structure):
//  - warp retile 64x32 -> 32x64: ah 16->8 regs, bT 8->4, rescale chain 16->8
//    HMUL2 per point; live set ~112 < 128 cap (R12 lesson: don't grow regs).
//  - bucket kernel reads dense g_traw (written by split_a) instead of
//    32768 strided loads from one CTA: ~20us off the pre-kernel time.
// ============================================================================

#define M_TOTAL   32768
#define N_TOTAL   1024
#define LDX       1025
#define PAD_M     33280
#define MAX_TILES 260

#define M_TILE    128
#define N_TILE    128
#define THREADS   256
#define D_CHUNKS  32                 // 1024 / 32
#define K_DC      32                 // K per d-chunk

// smem: A ring 3 x 8K | B ring 9 x 8K | perm | t
#define SM_B        24576
#define SM_PERM     98304
#define SM_T        98816
#define SMEM_TOTAL  99328

// -------- device scratch --------
__device__ __align__(16) __half g_A[(size_t)M_TOTAL * 1024];
__device__ __align__(16) __half g_P[(size_t)4 * 3072 * N_TOTAL];  // 25 MB
__device__ float g_traw[M_TOTAL];
__device__ int   g_perm[PAD_M];
__device__ float g_tp[PAD_M];
__device__ int   g_tile_int[MAX_TILES];

// -------- helpers --------
__device__ __forceinline__ uint32_t smem_u32(const void* p) {
    uint32_t a;
    asm("{ .reg .u64 t; cvta.to.shared.u64 t, %1; cvt.u32.u64 %0, t; }"
        : "=r"(a) : "l"(p));
    return a;
}

// A tile 128 rows x 32 halfs (64B/row) packed as 64 double-rows of 128B.
__device__ __forceinline__ uint32_t swzA32(int m, int k) {
    const uint32_t chunk = (uint32_t)(((m & 1) << 2) | ((k >> 3) & 3));
    const uint32_t dr = (uint32_t)(m >> 1);
    return dr * 128 + ((chunk ^ (dr & 7)) << 4) + (uint32_t)(k & 7) * 2;
}
// B tile 32 k-rows x 128 n (256B/row): chunk' = chunk ^ (k&7)  (proven).
__device__ __forceinline__ uint32_t swzB(int k, int n) {
    return (uint32_t)(k * 256 + ((((n >> 3) ^ (k & 7)) & 15) << 4) + (n & 7) * 2);
}

__device__ __forceinline__ void cp16(uint32_t dst, const void* src) {
    asm volatile("cp.async.cg.shared.global [%0], [%1], 16;"
                 :: "r"(dst), "l"(src) : "memory");
}

#define CP_COMMIT() asm volatile("cp.async.commit_group;" ::: "memory")
#define CP_WAIT(n)  asm volatile("cp.async.wait_group %0;" :: "n"(n) : "memory")

#define LDSM_X4(r0, r1, r2, r3, addr) \
    asm volatile("ldmatrix.sync.aligned.m8n8.x4.shared.b16 {%0,%1,%2,%3}, [%4];" \
                 : "=r"(r0), "=r"(r1), "=r"(r2), "=r"(r3) : "r"(addr))
#define LDSM_X4T(r0, r1, r2, r3, addr) \
    asm volatile("ldmatrix.sync.aligned.m8n8.x4.trans.shared.b16 {%0,%1,%2,%3}, [%4];" \
                 : "=r"(r0), "=r"(r1), "=r"(r2), "=r"(r3) : "r"(addr))

__device__ __forceinline__ void mma16816(float* c, const uint32_t* a, const uint32_t* b) {
    asm volatile(
        "mma.sync.aligned.m16n8k16.row.col.f32.f16.f16.f32 "
        "{%0,%1,%2,%3}, {%4,%5,%6,%7}, {%8,%9}, {%0,%1,%2,%3};"
        : "+f"(c[0]), "+f"(c[1]), "+f"(c[2]), "+f"(c[3])
        : "r"(a[0]), "r"(a[1]), "r"(a[2]), "r"(a[3]), "r"(b[0]), "r"(b[1]));
}

__device__ __forceinline__ uint32_t hmul2u(uint32_t a, uint32_t b) {
    __half2 r = __hmul2(*reinterpret_cast<__half2*>(&a),
                        *reinterpret_cast<__half2*>(&b));
    return *reinterpret_cast<uint32_t*>(&r);
}

// -------- pre-kernel: feats fp32 -> fp16 (+ dense t column) --------
__global__ void __launch_bounds__(256) split_a_kernel(const float* __restrict__ x) {
    size_t i = ((size_t)blockIdx.x * blockDim.x + threadIdx.x) * 4;
    if (i < (size_t)M_TOTAL * 1024) {
        const size_t m = i >> 10;
        const size_t d = i & 1023;
        const float* p = x + m * LDX + d;   // stride 1025: no LDG.128 allowed
        *reinterpret_cast<__half2*>(g_A + i)     = __floats2half2_rn(p[0], p[1]);
        *reinterpret_cast<__half2*>(g_A + i + 2) = __floats2half2_rn(p[2], p[3]);
        if (d == 0) g_traw[m] = x[m * LDX + 1024];
    }
}

// -------- pre-kernel: build P (4 intervals x 3 powers) --------
__global__ void __launch_bounds__(256) build_p_kernel(const float* __restrict__ w) {
    const size_t idx = (size_t)blockIdx.x * 256 + threadIdx.x;  // d*1024+e
    if (idx >= (size_t)1 << 20) return;
    const float w0 = w[idx];
    const float w1 = w[(size_t)1 * 1048576 + idx];
    const float w2 = w[(size_t)2 * 1048576 + idx];
    const float w3 = w[(size_t)3 * 1048576 + idx];
    const float w4 = w[(size_t)4 * 1048576 + idx];
    const float w5 = w[(size_t)5 * 1048576 + idx];
    float p0 = w0, p1 = w1, p2 = w2;
    #pragma unroll
    for (int i = 0; i < 4; ++i) {
        const size_t base = (size_t)i * 3 * 1048576 + idx;
        g_P[base]               = __float2half_rn(p0);
        g_P[base + 1048576]     = __float2half_rn(p1);
        g_P[base + 2 * 1048576] = __float2half_rn(p2);
        if (i == 0) { p0 += 0.0625f * w3; p1 -= 0.5f * w3; p2 += w3; }
        if (i == 1) { p0 += 0.25f   * w4; p1 -= 1.0f * w4; p2 += w4; }
        if (i == 2) { p0 += 0.5625f * w5; p1 -= 1.5f * w5; p2 += w5; }
    }
}

// -------- bucket kernel (1 CTA, dense g_traw) --------
__global__ void __launch_bounds__(1024) bucket_kernel() {
    extern __shared__ float t_cache[];
    __shared__ int s_cnt[4], s_cur[4];
    const int tid = threadIdx.x;
    if (tid < 4) s_cnt[tid] = 0;
    for (int i = tid; i < PAD_M; i += 1024) g_perm[i] = -1;
    for (int i = tid; i < MAX_TILES; i += 1024) g_tile_int[i] = -1;
    for (int i = tid; i < M_TOTAL; i += 1024)
        t_cache[i] = g_traw[i];          // dense, coalesced
    __syncthreads();

    const int base = tid * 32;
    int c[4] = {0, 0, 0, 0};
    #pragma unroll 4
    for (int r = 0; r < 32; ++r) {
        const float t = t_cache[base + r];
        c[(t > 0.25f) + (t > 0.5f) + (t > 0.75f)]++;
    }
    #pragma unroll
    for (int i = 0; i < 4; ++i) atomicAdd(&s_cnt[i], c[i]);
    __syncthreads();

    if (tid == 0) {
        int s = 0;
        #pragma unroll
        for (int i = 0; i < 4; ++i) {
            const int nt = (s_cnt[i] + 127) >> 7;
            const int ts = s >> 7;
            for (int j = 0; j < nt; ++j) g_tile_int[ts + j] = i;
            s_cur[i] = s;
            s += nt * 128;
        }
    }
    __syncthreads();

    int my[4];
    #pragma unroll
    for (int i = 0; i < 4; ++i) my[i] = atomicAdd(&s_cur[i], c[i]);
    for (int r = 0; r < 32; ++r) {
        const float t = t_cache[base + r];
        const int iv = (t > 0.25f) + (t > 0.5f) + (t > 0.75f);
        const int pos = my[iv]++;
        g_perm[pos] = base + r;
        g_tp[pos] = t;
    }
}

// -------- per-d-chunk loader: A (8K) + 3 B tiles (24K) --------
__device__ __forceinline__ void load_chunk(uint32_t sb, int j,
                                           const int* __restrict__ perm_s,
                                           const __half* __restrict__ Pbase,
                                           int n0, int tid) {
    const int d0 = j * K_DC;
    const uint32_t aBase = sb + (uint32_t)(j % 3) * 8192;
    #pragma unroll
    for (int r = 0; r < 2; ++r) {
        const int task = tid + r * 256;
        const int m = task >> 2;
        const int kc = task & 3;
        const int rg = perm_s[m] < 0 ? 0 : perm_s[m];
        cp16(aBase + swzA32(m, kc * 8), g_A + (size_t)rg * 1024 + d0 + kc * 8);
    }
    #pragma unroll
    for (int p = 0; p < 3; ++p) {
        const uint32_t bBase = sb + SM_B + (uint32_t)((j % 3) * 3 + p) * 8192;
        const __half* src = Pbase + (size_t)(p * 1024 + d0) * N_TOTAL + n0;
        #pragma unroll
        for (int r = 0; r < 2; ++r) {
            const int task = tid + r * 256;
            const int k = task >> 4;
            const int c = task & 15;
            cp16(bBase + swzB(k, c * 8), src + (size_t)k * N_TOTAL + c * 8);
        }
    }
}

// -------- main GEMM kernel: 2 CTAs/SM, warp tile 32x64 --------
__global__ void __launch_bounds__(THREADS, 2)
vclinear_gemm(const float* __restrict__ bias,
              float* __restrict__ out) {
    const int mt = blockIdx.x >> 3;
    const int interval = g_tile_int[mt];
    if (interval < 0) return;
    const int n0 = (blockIdx.x & 7) * N_TILE;

    extern __shared__ char smem[];
    const uint32_t sb = smem_u32(smem);
    const int tid = threadIdx.x;
    const int wid = tid >> 5;
    const int lane = tid & 31;
    const int warp_m = wid & 3;   // 0..3 -> 32 rows each
    const int warp_n = wid >> 2;  // 0..1 -> 64 cols each

    int* perm_s = reinterpret_cast<int*>(smem + SM_PERM);
    float* t_s  = reinterpret_cast<float*>(smem + SM_T);
    if (tid < M_TILE) {
        perm_s[tid] = g_perm[mt * M_TILE + tid];
        t_s[tid]    = g_tp[mt * M_TILE + tid];
    }
    __syncthreads();

    const __half* Pbase = g_P + (size_t)interval * 3072 * N_TOTAL;

    load_chunk(sb, 0, perm_s, Pbase, n0, tid);
    CP_COMMIT();
    load_chunk(sb, 1, perm_s, Pbase, n0, tid);
    CP_COMMIT();

    float acc[2][8][4];
    #pragma unroll
    for (int a = 0; a < 2; ++a)
        #pragma unroll
        for (int b = 0; b < 8; ++b)
            #pragma unroll
            for (int i = 0; i < 4; ++i) acc[a][b][i] = 0.0f;

    const int a_row   = warp_m * 32 + (lane & 15);
    const int a_koct  = (lane >> 4) * 8;
    const int b_krow  = (lane & 7) + (lane & 8);
    const int b_nhalf = (lane >> 4) * 8;
    const int t_row   = warp_m * 32 + (lane >> 2);

    // t broadcast (half2) for fragment rows r (bT0) and r+8 (bT1), m-frags 0..1
    uint32_t bT0[2], bT1[2];
    #pragma unroll
    for (int m = 0; m < 2; ++m) {
        __half2 h0 = __float2half2_rn(t_s[t_row + m * 16]);
        __half2 h1 = __float2half2_rn(t_s[t_row + m * 16 + 8]);
        bT0[m] = *reinterpret_cast<uint32_t*>(&h0);
        bT1[m] = *reinterpret_cast<uint32_t*>(&h1);
    }

    for (int j = 0; j < D_CHUNKS; ++j) {
        CP_WAIT(1);
        __syncthreads();

        if (j + 2 < D_CHUNKS)
            load_chunk(sb, j + 2, perm_s, Pbase, n0, tid);
        CP_COMMIT();

        const uint32_t aBase  = sb + (uint32_t)(j % 3) * 8192;
        const uint32_t bBase0 = sb + SM_B + (uint32_t)((j % 3) * 3) * 8192;

        #pragma unroll
        for (int ks = 0; ks < 2; ++ks) {
            const int k0 = ks * 16;
            uint32_t ah[2][4];
            #pragma unroll
            for (int m = 0; m < 2; ++m) {
                const uint32_t off = swzA32(a_row + m * 16, k0 + a_koct);
                LDSM_X4(ah[m][0], ah[m][1], ah[m][2], ah[m][3], aBase + off);
            }
            #pragma unroll
            for (int p = 0; p < 3; ++p) {
                const uint32_t bBase = bBase0 + (uint32_t)p * 8192;
                uint32_t bh[8][2];
                #pragma unroll
                for (int bt = 0; bt < 4; ++bt) {
                    const int n = warp_n * 64 + bt * 16 + b_nhalf;
                    const uint32_t off = swzB(k0 + b_krow, n);
                    LDSM_X4T(bh[2 * bt][0], bh[2 * bt][1],
                             bh[2 * bt + 1][0], bh[2 * bt + 1][1], bBase + off);
                }
                #pragma unroll
                for (int m = 0; m < 2; ++m)
                    #pragma unroll
                    for (int n = 0; n < 8; ++n)
                        mma16816(acc[m][n], ah[m], bh[n]);
                if (p < 2) {
                    // progressive scale: ah *= t (p1 sees t, p2 sees t^2)
                    #pragma unroll
                    for (int m = 0; m < 2; ++m) {
                        ah[m][0] = hmul2u(ah[m][0], bT0[m]);
                        ah[m][1] = hmul2u(ah[m][1], bT1[m]);
                        ah[m][2] = hmul2u(ah[m][2], bT0[m]);
                        ah[m][3] = hmul2u(ah[m][3], bT1[m]);
                    }
                }
            }
        }
    }

    // epilogue: scatter rows via perm, add bias
    #pragma unroll
    for (int m = 0; m < 2; ++m) {
        #pragma unroll
        for (int half = 0; half < 2; ++half) {
            const int rl = warp_m * 32 + m * 16 + (lane >> 2) + half * 8;
            const int rg = perm_s[rl];
            if (rg < 0) continue;
            float* orow = out + (size_t)rg * N_TOTAL;
            #pragma unroll
            for (int n = 0; n < 8; ++n) {
                const int col = n0 + warp_n * 64 + n * 8 + (lane & 3) * 2;
                float2 v;
                v.x = acc[m][n][half * 2 + 0] + __ldg(bias + col);
                v.y = acc[m][n][half * 2 + 1] + __ldg(bias + col + 1);
                *reinterpret_cast<float2*>(orow + col) = v;
            }
        }
    }
}

// -------- launch --------
extern "C" void kernel_launch(void* const* d_in, const int* in_sizes, int n_in,
                              void* d_out, int out_size) {
    const float* x    = (const float*)d_in[0];   // (32768, 1025)
    const float* w    = (const float*)d_in[1];   // (6,1024,1024)
    const float* bias = (const float*)d_in[2];   // (1024,)
    float* out = (float*)d_out;                  // (32768, 1024)

    static bool attr_set = false;
    if (!attr_set) {
        cudaFuncSetAttribute(vclinear_gemm,
                             cudaFuncAttributeMaxDynamicSharedMemorySize, SMEM_TOTAL);
        cudaFuncSetAttribute(bucket_kernel,
                             cudaFuncAttributeMaxDynamicSharedMemorySize,
                             M_TOTAL * (int)sizeof(float));
        attr_set = true;
    }

    split_a_kernel<<<(M_TOTAL * 1024 / 4 + 255) / 256, 256>>>(x);
    bucket_kernel<<<1, 1024, M_TOTAL * sizeof(float)>>>();
    build_p_kernel<<<(1 << 20) / 256, 256>>>(w);

    vclinear_gemm<<<MAX_TILES * 8, THREADS, SMEM_TOTAL>>>(bias, out);
}